// round 15
// baseline (speedup 1.0000x reference)
#include <cuda_runtime.h>
#include <cuda_fp16.h>
#include <cstdint>
#include <cstddef>

#define N_NODES 50000
#define N_EDGES 1600000
#define N_FEAT  128
#define KEEP_PROB 0.9f
#define SLOTS   80        // fixed per-row capacity; P(kept degree >= 80) ~ 1e-13
#define BUILD_BLOCK 320   // (N_EDGES/4) / 320 = 1250 blocks exactly
#define EPT 4             // edges per build thread (R13 config — best build)

// ---------------------------------------------------------------------------
// Scratch (allocation-free)
// ---------------------------------------------------------------------------
__device__ int      g_count[N_NODES];                 // zero at load; SpMM self-resets
__device__ uint32_t g_edge[(size_t)N_NODES * SLOTS];  // packed (col<<16 | fp16 val)
__device__ __half   g_xh[(size_t)N_NODES * N_FEAT];   // fp16 feature matrix, 12.8 MB

// ---------------------------------------------------------------------------
// threefry2x32 (JAX-compatible)
// ---------------------------------------------------------------------------
__host__ __device__ __forceinline__ uint32_t rotl32(uint32_t x, int r) {
#ifdef __CUDA_ARCH__
    return __funnelshift_l(x, x, r);
#else
    return (x << r) | (x >> (32 - r));
#endif
}

#define TF_ROUND(x0, x1, r) do { (x0) += (x1); (x1) = rotl32((x1), (r)); (x1) ^= (x0); } while (0)

__host__ __device__ __forceinline__ void threefry2x32(uint32_t k0, uint32_t k1,
                                                      uint32_t& x0, uint32_t& x1) {
    uint32_t ks2 = k0 ^ k1 ^ 0x1BD11BDAu;
    x0 += k0; x1 += k1;
    TF_ROUND(x0, x1, 13); TF_ROUND(x0, x1, 15); TF_ROUND(x0, x1, 26); TF_ROUND(x0, x1, 6);
    x0 += k1;  x1 += ks2 + 1u;
    TF_ROUND(x0, x1, 17); TF_ROUND(x0, x1, 29); TF_ROUND(x0, x1, 16); TF_ROUND(x0, x1, 24);
    x0 += ks2; x1 += k0 + 2u;
    TF_ROUND(x0, x1, 13); TF_ROUND(x0, x1, 15); TF_ROUND(x0, x1, 26); TF_ROUND(x0, x1, 6);
    x0 += k0;  x1 += k1 + 3u;
    TF_ROUND(x0, x1, 17); TF_ROUND(x0, x1, 29); TF_ROUND(x0, x1, 16); TF_ROUND(x0, x1, 24);
    x0 += k1;  x1 += ks2 + 4u;
    TF_ROUND(x0, x1, 13); TF_ROUND(x0, x1, 15); TF_ROUND(x0, x1, 26); TF_ROUND(x0, x1, 6);
    x0 += ks2; x1 += k0 + 5u;
}

__device__ __forceinline__ bool edge_keep(int e, uint32_t K0, uint32_t K1) {
    uint32_t x0 = 0u, x1 = (uint32_t)e;
    threefry2x32(K0, K1, x0, x1);
    const uint32_t bits = x0 ^ x1;
    const float u = __uint_as_float((bits >> 9) | 0x3f800000u) - 1.0f;
    return u < KEEP_PROB;
}

// ---------------------------------------------------------------------------
// Packed f32x2 helpers (Blackwell FFMA2 — only reachable via PTX fma.rn.f32x2)
// ---------------------------------------------------------------------------
__device__ __forceinline__ void fma2(unsigned long long& acc,
                                     unsigned long long a,
                                     unsigned long long b) {
    asm("fma.rn.f32x2 %0, %1, %2, %0;" : "+l"(acc) : "l"(a), "l"(b));
}
__device__ __forceinline__ unsigned long long pack2(float lo, float hi) {
    unsigned long long r;
    asm("mov.b64 %0, {%1, %2};" : "=l"(r) : "f"(lo), "f"(hi));
    return r;
}
__device__ __forceinline__ float2 unpack2(unsigned long long p) {
    float lo, hi;
    asm("mov.b64 {%0, %1}, %2;" : "=f"(lo), "=f"(hi) : "l"(p));
    return make_float2(lo, hi);
}

// ---------------------------------------------------------------------------
// Kernel 1: fused build (R13 shape — best measured). 4 independent edges +
// 4 float4 converts per thread.
// ---------------------------------------------------------------------------
__global__ __launch_bounds__(BUILD_BLOCK) void build_kernel(
    const float* __restrict__ x,
    const float* __restrict__ adj,
    const int*   __restrict__ row,
    const int*   __restrict__ col,
    uint32_t K0, uint32_t K1)
{
    const int t = blockIdx.x * BUILD_BLOCK + threadIdx.x;  // 400k threads exactly
    const int Q = N_EDGES / EPT;                           // 400000
    const float INV_KEEP = 1.0f / KEEP_PROB;

    // (a) x -> fp16: four coalesced float4s per thread (covers all 1.6M float4s)
    #pragma unroll
    for (int s = 0; s < EPT; ++s) {
        const int i = t + s * Q;
        const float4 v = __ldg(reinterpret_cast<const float4*>(x) + i);
        __half2 h0 = __floats2half2_rn(v.x, v.y);
        __half2 h1 = __floats2half2_rn(v.z, v.w);
        uint2 packed;
        packed.x = *reinterpret_cast<uint32_t*>(&h0);
        packed.y = *reinterpret_cast<uint32_t*>(&h1);
        reinterpret_cast<uint2*>(g_xh)[i] = packed;
    }

    // (b) four edges, independent chains
    int      r[EPT], p[EPT];
    uint32_t rec[EPT];
    bool     k[EPT];
    #pragma unroll
    for (int s = 0; s < EPT; ++s) {
        const int e = t + s * Q;
        k[s] = edge_keep(e, K0, K1);
        r[s] = __ldg(row + e);
        const int   c = __ldg(col + e);
        const float a = __ldg(adj + e);
        const __half hv = __float2half_rn(a * INV_KEEP);
        rec[s] = ((uint32_t)c << 16) | (uint32_t)__half_as_ushort(hv);
    }
    #pragma unroll
    for (int s = 0; s < EPT; ++s)
        if (k[s]) p[s] = atomicAdd(&g_count[r[s]], 1);
    #pragma unroll
    for (int s = 0; s < EPT; ++s)
        if (k[s] && p[s] < SLOTS)
            g_edge[(size_t)r[s] * SLOTS + p[s]] = rec[s];
}

// ---------------------------------------------------------------------------
// Kernel 2: SpMM — one warp per row. Main loop front-batches ALL 8 gather
// loads (addresses first, then 8 LDG.64s, then converts/FMAs) so ptxas can
// keep 8 loads in flight per lane. __launch_bounds__(256,3) lifts the 32-reg
// straitjacket that was serializing the loads (regs=32 -> ~3-4 in flight).
// ---------------------------------------------------------------------------
__device__ __forceinline__ void accum_h(
    uint2 h, uint32_t m,
    unsigned long long& a0, unsigned long long& a1)
{
    const float v = __half2float(__ushort_as_half((unsigned short)(m & 0xffffu)));
    const unsigned long long vv = pack2(v, v);
    const float2 f0 = __half22float2(*reinterpret_cast<const __half2*>(&h.x));
    const float2 f1 = __half22float2(*reinterpret_cast<const __half2*>(&h.y));
    fma2(a0, vv, pack2(f0.x, f0.y));
    fma2(a1, vv, pack2(f1.x, f1.y));
}

__global__ __launch_bounds__(256, 3) void spmm_kernel(
    float* __restrict__ out)
{
    const int r    = blockIdx.x * 8 + (threadIdx.x >> 5);  // 6250*8 == 50000
    const int lane = threadIdx.x & 31;

    int n = g_count[r];
    if (lane == 0) g_count[r] = 0;   // reset early; store latency overlaps loop
    if (n > SLOTS) n = SLOTS;
    const uint32_t* __restrict__ seg = g_edge + (size_t)r * SLOTS;
    const char* xh_lane = reinterpret_cast<const char*>(g_xh) + lane * 8;

    unsigned long long a0 = 0ull, a1 = 0ull;

    int i = 0;
    for (; i + 8 <= n; i += 8) {
        const uint4 sA = *reinterpret_cast<const uint4*>(seg + i);
        const uint4 sB = *reinterpret_cast<const uint4*>(seg + i + 4);
        uint32_t m[8] = {sA.x, sA.y, sA.z, sA.w, sB.x, sB.y, sB.z, sB.w};

        // phase 1: issue all 8 independent gathers
        uint2 h[8];
        #pragma unroll
        for (int j = 0; j < 8; ++j)
            h[j] = *reinterpret_cast<const uint2*>(
                xh_lane + ((m[j] >> 8) & 0x00FFFF00u));

        // phase 2: convert + packed FMA
        #pragma unroll
        for (int j = 0; j < 8; ++j)
            accum_h(h[j], m[j], a0, a1);
    }
    for (; i + 2 <= n; i += 2) {
        const uint32_t m0 = seg[i];
        const uint32_t m1 = seg[i + 1];
        const uint2 h0 = *reinterpret_cast<const uint2*>(xh_lane + ((m0 >> 8) & 0x00FFFF00u));
        const uint2 h1 = *reinterpret_cast<const uint2*>(xh_lane + ((m1 >> 8) & 0x00FFFF00u));
        accum_h(h0, m0, a0, a1);
        accum_h(h1, m1, a0, a1);
    }
    for (; i < n; ++i) {
        const uint32_t m = seg[i];
        const uint2 h = *reinterpret_cast<const uint2*>(xh_lane + ((m >> 8) & 0x00FFFF00u));
        accum_h(h, m, a0, a1);
    }

    const float2 r0 = unpack2(a0), r1 = unpack2(a1);
    reinterpret_cast<float4*>(out + (size_t)r * N_FEAT)[lane] =
        make_float4(r0.x, r0.y, r1.x, r1.y);
}

// ---------------------------------------------------------------------------
// Launch
// ---------------------------------------------------------------------------
extern "C" void kernel_launch(void* const* d_in, const int* in_sizes, int n_in,
                              void* d_out, int out_size) {
    const float* x   = (const float*)d_in[0];
    const float* adj = (const float*)d_in[1];
    const int*   row = (const int*)d_in[2];
    const int*   col = (const int*)d_in[3];
    float*       out = (float*)d_out;

    // mask_key = fold_in(key(42), 7) = threefry2x32(k=(0,42), x=(0,7))
    uint32_t f0 = 0u, f1 = 7u;
    threefry2x32(0u, 42u, f0, f1);

    static_assert((N_EDGES / EPT) % BUILD_BLOCK == 0, "build grid must tile exactly");
    static_assert(N_EDGES * 4 == N_NODES * N_FEAT, "convert work == edge work");
    static_assert(N_NODES % 8 == 0, "row grid must tile exactly");
    static_assert(SLOTS % 4 == 0, "seg uint4 loads need 16B alignment");

    build_kernel<<<(N_EDGES / EPT) / BUILD_BLOCK, BUILD_BLOCK>>>(x, adj, row, col, f0, f1);
    spmm_kernel<<<N_NODES / 8, 256>>>(out);
}

// round 16
// speedup vs baseline: 1.1833x; 1.1833x over previous
#include <cuda_runtime.h>
#include <cuda_fp16.h>
#include <cstdint>
#include <cstddef>

#define N_NODES 50000
#define N_EDGES 1600000
#define N_FEAT  128
#define KEEP_PROB 0.9f
#define SLOTS   80        // fixed per-row capacity; P(kept degree >= 80) ~ 1e-13
#define BUILD_BLOCK 320   // (N_EDGES/4) / 320 = 1250 blocks exactly
#define EPT 4             // edges per build thread (R13 config — best measured)

// ---------------------------------------------------------------------------
// Scratch (allocation-free)
// ---------------------------------------------------------------------------
__device__ int      g_count[N_NODES];                 // zero at load; SpMM self-resets
__device__ uint32_t g_edge[(size_t)N_NODES * SLOTS];  // packed (col<<16 | fp16 val)
__device__ __half   g_xh[(size_t)N_NODES * N_FEAT];   // fp16 feature matrix, 12.8 MB

// ---------------------------------------------------------------------------
// threefry2x32 (JAX-compatible)
// ---------------------------------------------------------------------------
__host__ __device__ __forceinline__ uint32_t rotl32(uint32_t x, int r) {
#ifdef __CUDA_ARCH__
    return __funnelshift_l(x, x, r);
#else
    return (x << r) | (x >> (32 - r));
#endif
}

#define TF_ROUND(x0, x1, r) do { (x0) += (x1); (x1) = rotl32((x1), (r)); (x1) ^= (x0); } while (0)

__host__ __device__ __forceinline__ void threefry2x32(uint32_t k0, uint32_t k1,
                                                      uint32_t& x0, uint32_t& x1) {
    uint32_t ks2 = k0 ^ k1 ^ 0x1BD11BDAu;
    x0 += k0; x1 += k1;
    TF_ROUND(x0, x1, 13); TF_ROUND(x0, x1, 15); TF_ROUND(x0, x1, 26); TF_ROUND(x0, x1, 6);
    x0 += k1;  x1 += ks2 + 1u;
    TF_ROUND(x0, x1, 17); TF_ROUND(x0, x1, 29); TF_ROUND(x0, x1, 16); TF_ROUND(x0, x1, 24);
    x0 += ks2; x1 += k0 + 2u;
    TF_ROUND(x0, x1, 13); TF_ROUND(x0, x1, 15); TF_ROUND(x0, x1, 26); TF_ROUND(x0, x1, 6);
    x0 += k0;  x1 += k1 + 3u;
    TF_ROUND(x0, x1, 17); TF_ROUND(x0, x1, 29); TF_ROUND(x0, x1, 16); TF_ROUND(x0, x1, 24);
    x0 += k1;  x1 += ks2 + 4u;
    TF_ROUND(x0, x1, 13); TF_ROUND(x0, x1, 15); TF_ROUND(x0, x1, 26); TF_ROUND(x0, x1, 6);
    x0 += ks2; x1 += k0 + 5u;
}

__device__ __forceinline__ bool edge_keep(int e, uint32_t K0, uint32_t K1) {
    uint32_t x0 = 0u, x1 = (uint32_t)e;
    threefry2x32(K0, K1, x0, x1);
    const uint32_t bits = x0 ^ x1;
    const float u = __uint_as_float((bits >> 9) | 0x3f800000u) - 1.0f;
    return u < KEEP_PROB;
}

// ---------------------------------------------------------------------------
// Packed f32x2 helpers (Blackwell FFMA2 — only reachable via PTX fma.rn.f32x2)
// ---------------------------------------------------------------------------
__device__ __forceinline__ void fma2(unsigned long long& acc,
                                     unsigned long long a,
                                     unsigned long long b) {
    asm("fma.rn.f32x2 %0, %1, %2, %0;" : "+l"(acc) : "l"(a), "l"(b));
}
__device__ __forceinline__ unsigned long long pack2(float lo, float hi) {
    unsigned long long r;
    asm("mov.b64 %0, {%1, %2};" : "=l"(r) : "f"(lo), "f"(hi));
    return r;
}
__device__ __forceinline__ float2 unpack2(unsigned long long p) {
    float lo, hi;
    asm("mov.b64 {%0, %1}, %2;" : "=f"(lo), "=f"(hi) : "l"(p));
    return make_float2(lo, hi);
}

// ---------------------------------------------------------------------------
// Kernel 1: fused build (R13 shape — best measured). 4 independent edges +
// 4 float4 converts per thread.
// ---------------------------------------------------------------------------
__global__ __launch_bounds__(BUILD_BLOCK) void build_kernel(
    const float* __restrict__ x,
    const float* __restrict__ adj,
    const int*   __restrict__ row,
    const int*   __restrict__ col,
    uint32_t K0, uint32_t K1)
{
    const int t = blockIdx.x * BUILD_BLOCK + threadIdx.x;  // 400k threads exactly
    const int Q = N_EDGES / EPT;                           // 400000
    const float INV_KEEP = 1.0f / KEEP_PROB;

    // (a) x -> fp16: four coalesced float4s per thread (covers all 1.6M float4s)
    #pragma unroll
    for (int s = 0; s < EPT; ++s) {
        const int i = t + s * Q;
        const float4 v = __ldg(reinterpret_cast<const float4*>(x) + i);
        __half2 h0 = __floats2half2_rn(v.x, v.y);
        __half2 h1 = __floats2half2_rn(v.z, v.w);
        uint2 packed;
        packed.x = *reinterpret_cast<uint32_t*>(&h0);
        packed.y = *reinterpret_cast<uint32_t*>(&h1);
        reinterpret_cast<uint2*>(g_xh)[i] = packed;
    }

    // (b) four edges, independent chains
    int      r[EPT], p[EPT];
    uint32_t rec[EPT];
    bool     k[EPT];
    #pragma unroll
    for (int s = 0; s < EPT; ++s) {
        const int e = t + s * Q;
        k[s] = edge_keep(e, K0, K1);
        r[s] = __ldg(row + e);
        const int   c = __ldg(col + e);
        const float a = __ldg(adj + e);
        const __half hv = __float2half_rn(a * INV_KEEP);
        rec[s] = ((uint32_t)c << 16) | (uint32_t)__half_as_ushort(hv);
    }
    #pragma unroll
    for (int s = 0; s < EPT; ++s)
        if (k[s]) p[s] = atomicAdd(&g_count[r[s]], 1);
    #pragma unroll
    for (int s = 0; s < EPT; ++s)
        if (k[s] && p[s] < SLOTS)
            g_edge[(size_t)r[s] * SLOTS + p[s]] = rec[s];
}

// ---------------------------------------------------------------------------
// Kernel 2: SpMM — one warp per row, 8-edge unroll (8 LDG.64 gathers in
// flight per lane), packed-f32x2 accumulation. Lane l owns features [4l,4l+4).
// R13-exact structure: regs=32 / ~64 warps per SM is the measured optimum
// (R15 proved trading occupancy for registers loses 4x). Do not restructure.
// ---------------------------------------------------------------------------
__device__ __forceinline__ void edge_accum(
    uint32_t m, const char* xh_lane,
    unsigned long long& a0, unsigned long long& a1)
{
    // byte offset of row (m>>16): *256B == ((m >> 8) & 0xFFFF00)
    const uint2 h = *reinterpret_cast<const uint2*>(
        xh_lane + ((m >> 8) & 0x00FFFF00u));
    const float v = __half2float(__ushort_as_half((unsigned short)(m & 0xffffu)));
    const unsigned long long vv = pack2(v, v);
    const float2 f0 = __half22float2(*reinterpret_cast<const __half2*>(&h.x));
    const float2 f1 = __half22float2(*reinterpret_cast<const __half2*>(&h.y));
    fma2(a0, vv, pack2(f0.x, f0.y));
    fma2(a1, vv, pack2(f1.x, f1.y));
}

__global__ __launch_bounds__(256) void spmm_kernel(
    float* __restrict__ out)
{
    const int r    = blockIdx.x * 8 + (threadIdx.x >> 5);  // 6250*8 == 50000
    const int lane = threadIdx.x & 31;

    int n = g_count[r];
    if (lane == 0) g_count[r] = 0;   // reset early; store latency overlaps loop
    if (n > SLOTS) n = SLOTS;
    const uint32_t* __restrict__ seg = g_edge + (size_t)r * SLOTS;
    const char* xh_lane = reinterpret_cast<const char*>(g_xh) + lane * 8;

    unsigned long long a0 = 0ull, a1 = 0ull;

    int i = 0;
    for (; i + 8 <= n; i += 8) {
        // two 16B uniform loads fetch 8 edge records; 8 gathers go in flight
        const uint4 sA = *reinterpret_cast<const uint4*>(seg + i);
        const uint4 sB = *reinterpret_cast<const uint4*>(seg + i + 4);
        edge_accum(sA.x, xh_lane, a0, a1);
        edge_accum(sA.y, xh_lane, a0, a1);
        edge_accum(sA.z, xh_lane, a0, a1);
        edge_accum(sA.w, xh_lane, a0, a1);
        edge_accum(sB.x, xh_lane, a0, a1);
        edge_accum(sB.y, xh_lane, a0, a1);
        edge_accum(sB.z, xh_lane, a0, a1);
        edge_accum(sB.w, xh_lane, a0, a1);
    }
    for (; i + 2 <= n; i += 2) {
        const uint32_t m0 = seg[i];
        const uint32_t m1 = seg[i + 1];
        edge_accum(m0, xh_lane, a0, a1);
        edge_accum(m1, xh_lane, a0, a1);
    }
    for (; i < n; ++i)
        edge_accum(seg[i], xh_lane, a0, a1);

    const float2 r0 = unpack2(a0), r1 = unpack2(a1);
    reinterpret_cast<float4*>(out + (size_t)r * N_FEAT)[lane] =
        make_float4(r0.x, r0.y, r1.x, r1.y);
}

// ---------------------------------------------------------------------------
// Launch
// ---------------------------------------------------------------------------
extern "C" void kernel_launch(void* const* d_in, const int* in_sizes, int n_in,
                              void* d_out, int out_size) {
    const float* x   = (const float*)d_in[0];
    const float* adj = (const float*)d_in[1];
    const int*   row = (const int*)d_in[2];
    const int*   col = (const int*)d_in[3];
    float*       out = (float*)d_out;

    // mask_key = fold_in(key(42), 7) = threefry2x32(k=(0,42), x=(0,7))
    uint32_t f0 = 0u, f1 = 7u;
    threefry2x32(0u, 42u, f0, f1);

    static_assert((N_EDGES / EPT) % BUILD_BLOCK == 0, "build grid must tile exactly");
    static_assert(N_EDGES * 4 == N_NODES * N_FEAT, "convert work == edge work");
    static_assert(N_NODES % 8 == 0, "row grid must tile exactly");
    static_assert(SLOTS % 4 == 0, "seg uint4 loads need 16B alignment");

    build_kernel<<<(N_EDGES / EPT) / BUILD_BLOCK, BUILD_BLOCK>>>(x, adj, row, col, f0, f1);
    spmm_kernel<<<N_NODES / 8, 256>>>(out);
}

// round 17
// speedup vs baseline: 2.7774x; 2.3471x over previous
#include <cuda_runtime.h>
#include <cuda_fp16.h>
#include <cstdint>
#include <cstddef>

#define N_NODES 50000
#define N_EDGES 1600000
#define N_FEAT  128
#define KEEP_PROB 0.9f
#define SLOTS   80        // fixed per-row capacity; P(kept degree >= 80) ~ 1e-13
#define BUILD_BLOCK 320   // (N_EDGES/4) / 320 = 1250 blocks exactly
#define EPT 4             // edges per build thread (best measured)

// ---------------------------------------------------------------------------
// Scratch (allocation-free)
// ---------------------------------------------------------------------------
__device__ int      g_count[N_NODES];                 // zero at load; SpMM self-resets
__device__ uint32_t g_edge[(size_t)N_NODES * SLOTS];  // packed (col<<16 | fp16 val)
__device__ __half   g_xh[(size_t)N_NODES * N_FEAT];   // fp16 feature matrix, 12.8 MB

// ---------------------------------------------------------------------------
// threefry2x32 (JAX-compatible)
// ---------------------------------------------------------------------------
__host__ __device__ __forceinline__ uint32_t rotl32(uint32_t x, int r) {
#ifdef __CUDA_ARCH__
    return __funnelshift_l(x, x, r);
#else
    return (x << r) | (x >> (32 - r));
#endif
}

#define TF_ROUND(x0, x1, r) do { (x0) += (x1); (x1) = rotl32((x1), (r)); (x1) ^= (x0); } while (0)

__host__ __device__ __forceinline__ void threefry2x32(uint32_t k0, uint32_t k1,
                                                      uint32_t& x0, uint32_t& x1) {
    uint32_t ks2 = k0 ^ k1 ^ 0x1BD11BDAu;
    x0 += k0; x1 += k1;
    TF_ROUND(x0, x1, 13); TF_ROUND(x0, x1, 15); TF_ROUND(x0, x1, 26); TF_ROUND(x0, x1, 6);
    x0 += k1;  x1 += ks2 + 1u;
    TF_ROUND(x0, x1, 17); TF_ROUND(x0, x1, 29); TF_ROUND(x0, x1, 16); TF_ROUND(x0, x1, 24);
    x0 += ks2; x1 += k0 + 2u;
    TF_ROUND(x0, x1, 13); TF_ROUND(x0, x1, 15); TF_ROUND(x0, x1, 26); TF_ROUND(x0, x1, 6);
    x0 += k0;  x1 += k1 + 3u;
    TF_ROUND(x0, x1, 17); TF_ROUND(x0, x1, 29); TF_ROUND(x0, x1, 16); TF_ROUND(x0, x1, 24);
    x0 += k1;  x1 += ks2 + 4u;
    TF_ROUND(x0, x1, 13); TF_ROUND(x0, x1, 15); TF_ROUND(x0, x1, 26); TF_ROUND(x0, x1, 6);
    x0 += ks2; x1 += k0 + 5u;
}

__device__ __forceinline__ bool edge_keep(int e, uint32_t K0, uint32_t K1) {
    uint32_t x0 = 0u, x1 = (uint32_t)e;
    threefry2x32(K0, K1, x0, x1);
    const uint32_t bits = x0 ^ x1;
    const float u = __uint_as_float((bits >> 9) | 0x3f800000u) - 1.0f;
    return u < KEEP_PROB;
}

// ---------------------------------------------------------------------------
// Packed f32x2 helpers (Blackwell FFMA2 — only reachable via PTX fma.rn.f32x2)
// ---------------------------------------------------------------------------
__device__ __forceinline__ void fma2(unsigned long long& acc,
                                     unsigned long long a,
                                     unsigned long long b) {
    asm("fma.rn.f32x2 %0, %1, %2, %0;" : "+l"(acc) : "l"(a), "l"(b));
}
__device__ __forceinline__ unsigned long long pack2(float lo, float hi) {
    unsigned long long r;
    asm("mov.b64 %0, {%1, %2};" : "=l"(r) : "f"(lo), "f"(hi));
    return r;
}
__device__ __forceinline__ float2 unpack2(unsigned long long p) {
    float lo, hi;
    asm("mov.b64 {%0, %1}, %2;" : "=f"(lo), "=f"(hi) : "l"(p));
    return make_float2(lo, hi);
}

// ---------------------------------------------------------------------------
// Kernel 1: fused build (R16 exact — best measured ~21us). 4 independent
// edges + 4 float4 converts per thread; multiply instead of divide.
// ---------------------------------------------------------------------------
__global__ __launch_bounds__(BUILD_BLOCK) void build_kernel(
    const float* __restrict__ x,
    const float* __restrict__ adj,
    const int*   __restrict__ row,
    const int*   __restrict__ col,
    uint32_t K0, uint32_t K1)
{
    const int t = blockIdx.x * BUILD_BLOCK + threadIdx.x;  // 400k threads exactly
    const int Q = N_EDGES / EPT;                           // 400000
    const float INV_KEEP = 1.0f / KEEP_PROB;

    // (a) x -> fp16: four coalesced float4s per thread (covers all 1.6M float4s)
    #pragma unroll
    for (int s = 0; s < EPT; ++s) {
        const int i = t + s * Q;
        const float4 v = __ldg(reinterpret_cast<const float4*>(x) + i);
        __half2 h0 = __floats2half2_rn(v.x, v.y);
        __half2 h1 = __floats2half2_rn(v.z, v.w);
        uint2 packed;
        packed.x = *reinterpret_cast<uint32_t*>(&h0);
        packed.y = *reinterpret_cast<uint32_t*>(&h1);
        reinterpret_cast<uint2*>(g_xh)[i] = packed;
    }

    // (b) four edges, independent chains
    int      r[EPT], p[EPT];
    uint32_t rec[EPT];
    bool     k[EPT];
    #pragma unroll
    for (int s = 0; s < EPT; ++s) {
        const int e = t + s * Q;
        k[s] = edge_keep(e, K0, K1);
        r[s] = __ldg(row + e);
        const int   c = __ldg(col + e);
        const float a = __ldg(adj + e);
        const __half hv = __float2half_rn(a * INV_KEEP);
        rec[s] = ((uint32_t)c << 16) | (uint32_t)__half_as_ushort(hv);
    }
    #pragma unroll
    for (int s = 0; s < EPT; ++s)
        if (k[s]) p[s] = atomicAdd(&g_count[r[s]], 1);
    #pragma unroll
    for (int s = 0; s < EPT; ++s)
        if (k[s] && p[s] < SLOTS)
            g_edge[(size_t)r[s] * SLOTS + p[s]] = rec[s];
}

// ---------------------------------------------------------------------------
// Kernel 2: SpMM — R13 byte-exact (38.2us measured). One warp per row,
// 8-edge unroll, packed-f32x2 accumulation, counter reset at the END.
// regs=32 / 64 warps per SM is load-bearing: R15 (more regs) lost 4x,
// R16 (early reset, regs 34) lost 3.3x. DO NOT touch the prologue.
// ---------------------------------------------------------------------------
__device__ __forceinline__ void edge_accum(
    uint32_t m, const char* xh_lane,
    unsigned long long& a0, unsigned long long& a1)
{
    // byte offset of row (m>>16): *256B == ((m >> 8) & 0xFFFF00)
    const uint2 h = *reinterpret_cast<const uint2*>(
        xh_lane + ((m >> 8) & 0x00FFFF00u));
    const float v = __half2float(__ushort_as_half((unsigned short)(m & 0xffffu)));
    const unsigned long long vv = pack2(v, v);
    const float2 f0 = __half22float2(*reinterpret_cast<const __half2*>(&h.x));
    const float2 f1 = __half22float2(*reinterpret_cast<const __half2*>(&h.y));
    fma2(a0, vv, pack2(f0.x, f0.y));
    fma2(a1, vv, pack2(f1.x, f1.y));
}

__global__ __launch_bounds__(256) void spmm_kernel(
    float* __restrict__ out)
{
    const int r    = blockIdx.x * 8 + (threadIdx.x >> 5);  // 6250*8 == 50000
    const int lane = threadIdx.x & 31;

    int n = g_count[r];
    if (n > SLOTS) n = SLOTS;
    const uint32_t* __restrict__ seg = g_edge + (size_t)r * SLOTS;
    const char* xh_lane = reinterpret_cast<const char*>(g_xh) + lane * 8;

    unsigned long long a0 = 0ull, a1 = 0ull;

    int i = 0;
    for (; i + 8 <= n; i += 8) {
        // two 16B uniform loads fetch 8 edge records; 8 gathers go in flight
        const uint4 sA = *reinterpret_cast<const uint4*>(seg + i);
        const uint4 sB = *reinterpret_cast<const uint4*>(seg + i + 4);
        edge_accum(sA.x, xh_lane, a0, a1);
        edge_accum(sA.y, xh_lane, a0, a1);
        edge_accum(sA.z, xh_lane, a0, a1);
        edge_accum(sA.w, xh_lane, a0, a1);
        edge_accum(sB.x, xh_lane, a0, a1);
        edge_accum(sB.y, xh_lane, a0, a1);
        edge_accum(sB.z, xh_lane, a0, a1);
        edge_accum(sB.w, xh_lane, a0, a1);
    }
    for (; i + 2 <= n; i += 2) {
        const uint32_t m0 = seg[i];
        const uint32_t m1 = seg[i + 1];
        edge_accum(m0, xh_lane, a0, a1);
        edge_accum(m1, xh_lane, a0, a1);
    }
    for (; i < n; ++i)
        edge_accum(seg[i], xh_lane, a0, a1);

    const float2 r0 = unpack2(a0), r1 = unpack2(a1);
    reinterpret_cast<float4*>(out + (size_t)r * N_FEAT)[lane] =
        make_float4(r0.x, r0.y, r1.x, r1.y);

    if (lane == 0) g_count[r] = 0;   // self-restore for next graph replay
}

// ---------------------------------------------------------------------------
// Launch
// ---------------------------------------------------------------------------
extern "C" void kernel_launch(void* const* d_in, const int* in_sizes, int n_in,
                              void* d_out, int out_size) {
    const float* x   = (const float*)d_in[0];
    const float* adj = (const float*)d_in[1];
    const int*   row = (const int*)d_in[2];
    const int*   col = (const int*)d_in[3];
    float*       out = (float*)d_out;

    // mask_key = fold_in(key(42), 7) = threefry2x32(k=(0,42), x=(0,7))
    uint32_t f0 = 0u, f1 = 7u;
    threefry2x32(0u, 42u, f0, f1);

    static_assert((N_EDGES / EPT) % BUILD_BLOCK == 0, "build grid must tile exactly");
    static_assert(N_EDGES * 4 == N_NODES * N_FEAT, "convert work == edge work");
    static_assert(N_NODES % 8 == 0, "row grid must tile exactly");
    static_assert(SLOTS % 4 == 0, "seg uint4 loads need 16B alignment");

    build_kernel<<<(N_EDGES / EPT) / BUILD_BLOCK, BUILD_BLOCK>>>(x, adj, row, col, f0, f1);
    spmm_kernel<<<N_NODES / 8, 256>>>(out);
}